// round 6
// baseline (speedup 1.0000x reference)
#include <cuda_runtime.h>
#include <cstdint>

// DeepUDI, two streaming kernels.
// K1 (attention): per-(n,r) CTA. ALL weight bytes (w/qw/kw = 80KB) are issued
//   as cp.async at kernel entry in 4 commit groups; compute phases wait_group
//   progressively, so DRAM streaming is fully decoupled from the dependency
//   chain (J -> Jq -> v).
// K2 (GRU): unchanged from R5 (76% DRAM, near floor).

#define NN   2048
#define RR   2
#define KK   32
#define DD   64
#define FF   64
#define DD2  128
#define HPAD 68

__device__ float df_g[NN * RR * FF];   // 1MB scratch

__device__ __forceinline__ float sigm(float v) {
    return 1.f / (1.f + __expf(-v));
}

__device__ __forceinline__ void cp16(void* dst_smem, const void* src_gmem) {
    uint32_t d = (uint32_t)__cvta_generic_to_shared(dst_smem);
    asm volatile("cp.async.cg.shared.global [%0], [%1], 16;\n"
                 :: "r"(d), "l"(src_gmem));
}
#define CP_COMMIT() asm volatile("cp.async.commit_group;\n" ::: "memory")
#define CP_WAIT(N)  asm volatile("cp.async.wait_group %0;\n" :: "n"(N) : "memory")

// dynamic smem layout for attn (all offsets 16B-aligned)
struct AttnSmem {
    float w[DD * FF];        // 16KB
    float qw[FF * DD2];      // 32KB
    float kw[FF * DD2];      // 32KB
    float hn[KK][HPAD];      // 8.5KB (hn, later overwritten with Hn)
    float h[DD];
    float J[FF];
    float jqp[2][DD2];
    float v[FF];
    float sc[KK];
    int   nb[KK];
    int   flags[2];
};
#define ATTN_SMEM_BYTES ((int)sizeof(AttnSmem))

// ===================== Kernel 1: attention -> df ========================
__global__ __launch_bounds__(256)
void attn_kernel(const void* __restrict__ x_raw,
                 const void* __restrict__ nb_raw,
                 const float* __restrict__ embed,
                 const float* __restrict__ w,
                 const float* __restrict__ qw,
                 const float* __restrict__ kw)
{
    extern __shared__ __align__(16) char smem_raw[];
    AttnSmem* S = (AttnSmem*)smem_raw;

    const int nr  = blockIdx.x;        // n*RR + r
    const int n   = nr >> 1;
    const int tid = threadIdx.x;

    // ---- group A: stage w (1024 float4) --------------------------------
    {
        const float4* src = (const float4*)(w + (long long)nr * (DD * FF));
        float4* dst = (float4*)S->w;
        #pragma unroll
        for (int j = 0; j < 4; j++)
            cp16(dst + tid + 256 * j, src + tid + 256 * j);
        CP_COMMIT();
    }
    // ---- dtype detection (x = arange; int64 view has word[1]==0) -------
    if (tid == 0) {
        const int* xi = (const int*)x_raw;
        int idx64 = (xi[1] == 0) ? 1 : 0;
        S->flags[0] = idx64;
        S->flags[1] = idx64 ? (int)((const long long*)x_raw)[n] : xi[n];
    }
    __syncthreads();
    const int idx64 = S->flags[0];
    const int xn    = S->flags[1];

    if (tid < KK) {
        long long base = (long long)nr * KK + tid;
        S->nb[tid] = idx64 ? (int)((const long long*)nb_raw)[base]
                           : ((const int*)nb_raw)[base];
    }
    if (tid >= 64 && tid < 128)
        S->h[tid - 64] = embed[(long long)xn * DD + (tid - 64)];
    __syncthreads();

    // ---- group B: gather hn (512 float4, embed is L2-resident) ---------
    #pragma unroll
    for (int j = 0; j < 2; j++) {
        int i  = tid + 256 * j;
        int k  = i >> 4;
        int dv = i & 15;
        cp16(&S->hn[k][dv * 4],
             embed + (long long)S->nb[k] * DD + dv * 4);
    }
    CP_COMMIT();

    // ---- group C: stage qw (2048 float4) -------------------------------
    {
        const float4* src = (const float4*)(qw + (long long)nr * (FF * DD2));
        float4* dst = (float4*)S->qw;
        #pragma unroll
        for (int j = 0; j < 8; j++)
            cp16(dst + tid + 256 * j, src + tid + 256 * j);
        CP_COMMIT();
    }
    // ---- group D: stage kw (2048 float4) -------------------------------
    {
        const float4* src = (const float4*)(kw + (long long)nr * (FF * DD2));
        float4* dst = (float4*)S->kw;
        #pragma unroll
        for (int j = 0; j < 8; j++)
            cp16(dst + tid + 256 * j, src + tid + 256 * j);
        CP_COMMIT();
    }

    CP_WAIT(2);            // w + hn arrived (qw, kw still in flight)
    __syncthreads();

    // ---- phase 1: Hn = hn @ w : thread = (k, f-octant) -----------------
    const int k  = tid >> 3;
    const int g  = tid & 7;
    const int f0 = g * 8;

    float acc[8];
    #pragma unroll
    for (int j = 0; j < 8; j++) acc[j] = 0.f;

    #pragma unroll 4
    for (int d = 0; d < DD; d++) {
        float a = S->hn[k][d];
        float4 w0 = *(const float4*)&S->w[d * FF + f0];
        float4 w1 = *(const float4*)&S->w[d * FF + f0 + 4];
        acc[0] += a * w0.x; acc[1] += a * w0.y;
        acc[2] += a * w0.z; acc[3] += a * w0.w;
        acc[4] += a * w1.x; acc[5] += a * w1.y;
        acc[6] += a * w1.z; acc[7] += a * w1.w;
    }
    // J = h @ w (smem-resident)
    if (tid < FF) {
        float ja = 0.f;
        #pragma unroll 8
        for (int d = 0; d < DD; d++)
            ja += S->h[d] * S->w[d * FF + tid];
        S->J[tid] = ja;
    }
    __syncthreads();       // all hn reads done; J published

    // overwrite hn with Hn
    *(float4*)&S->hn[k][f0]     = make_float4(acc[0], acc[1], acc[2], acc[3]);
    *(float4*)&S->hn[k][f0 + 4] = make_float4(acc[4], acc[5], acc[6], acc[7]);

    CP_WAIT(1);            // qw arrived
    __syncthreads();

    // ---- phase 2: Jq[e] = sum_f J[f]*qw[f,e] : (e, f-half) partials ----
    {
        int e  = tid & 127;
        int fh = tid >> 7;
        float a2 = 0.f;
        #pragma unroll 8
        for (int f = fh * 32; f < fh * 32 + 32; f++)
            a2 += S->J[f] * S->qw[f * DD2 + e];
        S->jqp[fh][e] = a2;
    }

    CP_WAIT(0);            // kw arrived
    __syncthreads();

    // ---- phase 3: v[f] = sum_e kw[f,e]*Jq[e] : 8 warps x 8 rows --------
    {
        int warp = tid >> 5, lane = tid & 31;
        float4 q0 = ((const float4*)S->jqp[0])[lane];
        float4 q1 = ((const float4*)S->jqp[1])[lane];
        float4 q  = make_float4(q0.x + q1.x, q0.y + q1.y,
                                q0.z + q1.z, q0.w + q1.w);
        #pragma unroll
        for (int i = 0; i < 8; i++) {
            int f = warp * 8 + i;
            float4 kv = *(const float4*)&S->kw[f * DD2 + lane * 4];
            float p = kv.x * q.x + kv.y * q.y + kv.z * q.z + kv.w * q.w;
            #pragma unroll
            for (int off = 16; off > 0; off >>= 1)
                p += __shfl_xor_sync(0xffffffffu, p, off);
            if (lane == 0) S->v[f] = p;
        }
    }
    __syncthreads();

    // ---- phase 4: scores[k] = Hn[k,:].v (live accs, 8-lane reduce) -----
    {
        float s = 0.f;
        #pragma unroll
        for (int j = 0; j < 8; j++) s += acc[j] * S->v[f0 + j];
        s += __shfl_xor_sync(0xffffffffu, s, 1);
        s += __shfl_xor_sync(0xffffffffu, s, 2);
        s += __shfl_xor_sync(0xffffffffu, s, 4);
        if (g == 0) S->sc[k] = s;
    }
    __syncthreads();

    // ---- phase 5: softmax over K=32 (warp 0) ---------------------------
    if (tid < 32) {
        float s = S->sc[tid];
        float m = s;
        #pragma unroll
        for (int off = 16; off > 0; off >>= 1)
            m = fmaxf(m, __shfl_xor_sync(0xffffffffu, m, off));
        float e = __expf(s - m);
        float sum = e;
        #pragma unroll
        for (int off = 16; off > 0; off >>= 1)
            sum += __shfl_xor_sync(0xffffffffu, sum, off);
        S->sc[tid] = e / sum;
    }
    __syncthreads();

    // ---- phase 6: df[f] = sum_k E[k]*Hn[k,f] -> scratch ----------------
    if (tid < FF) {
        float da = 0.f;
        #pragma unroll
        for (int kk = 0; kk < KK; kk++)
            da += S->sc[kk] * S->hn[kk][tid];
        df_g[(long long)nr * FF + tid] = da;
    }
}

// ===================== Kernel 2: GRU + combine (unchanged) ==============
__global__ __launch_bounds__(256)
void gru_kernel(const void* __restrict__ x_raw,
                const float* __restrict__ embed,
                const float* __restrict__ Wx,
                const float* __restrict__ Wn,
                const float* __restrict__ bx,
                const float* __restrict__ bn,
                float* __restrict__ out)
{
    __shared__ float h_s[DD];
    __shared__ float df_s[RR][FF];
    __shared__ __align__(16) float part[RR][8][5][FF];
    __shared__ __align__(16) float red[RR][6][FF];
    __shared__ float rdf_s[RR][FF];
    __shared__ float gru_s[RR][FF];
    __shared__ int   flags[2];

    const int n   = blockIdx.x;
    const int tid = threadIdx.x;
    const int r   = tid >> 7;
    const int wg  = tid & 127;

    if (tid == 0) {
        const int* xi = (const int*)x_raw;
        int idx64 = (xi[1] == 0) ? 1 : 0;
        flags[0] = idx64;
        flags[1] = idx64 ? (int)((const long long*)x_raw)[n] : xi[n];
    }
    __syncthreads();
    const int xn = flags[1];

    if (tid < DD) h_s[tid] = embed[(long long)xn * DD + tid];
    if (wg < FF)  df_s[r][wg] = df_g[((long long)n * RR + r) * FF + wg];
    __syncthreads();

    const long long nr = (long long)n * RR + r;
    const float* Wxr = Wx + nr * (3 * DD * FF);
    const float* Wnr = Wn + nr * (3 * FF * FF);
    const float* bxr = bx + nr * (3 * FF);
    const float* bnr = bn + nr * (3 * FF);

    const int fg = wg & 15;
    const int ds = wg >> 4;
    const int f4 = fg * 4;

    float4 a0 = make_float4(0,0,0,0), a1 = a0, a2v = a0, a3 = a0, a4 = a0;
    #pragma unroll
    for (int dd = 0; dd < 8; dd++) {
        int d = ds * 8 + dd;
        float hd  = h_s[d];
        float dfd = df_s[r][d];
        float4 x0 = __ldg((const float4*)(Wxr + (0*DD + d)*FF + f4));
        float4 x1 = __ldg((const float4*)(Wxr + (1*DD + d)*FF + f4));
        float4 x2 = __ldg((const float4*)(Wxr + (2*DD + d)*FF + f4));
        float4 n0 = __ldg((const float4*)(Wnr + (0*FF + d)*FF + f4));
        float4 n1 = __ldg((const float4*)(Wnr + (1*FF + d)*FF + f4));
        a0.x += hd*x0.x;  a0.y += hd*x0.y;  a0.z += hd*x0.z;  a0.w += hd*x0.w;
        a1.x += hd*x1.x;  a1.y += hd*x1.y;  a1.z += hd*x1.z;  a1.w += hd*x1.w;
        a2v.x+= hd*x2.x;  a2v.y+= hd*x2.y;  a2v.z+= hd*x2.z;  a2v.w+= hd*x2.w;
        a3.x += dfd*n0.x; a3.y += dfd*n0.y; a3.z += dfd*n0.z; a3.w += dfd*n0.w;
        a4.x += dfd*n1.x; a4.y += dfd*n1.y; a4.z += dfd*n1.z; a4.w += dfd*n1.w;
    }
    *(float4*)&part[r][ds][0][f4] = a0;
    *(float4*)&part[r][ds][1][f4] = a1;
    *(float4*)&part[r][ds][2][f4] = a2v;
    *(float4*)&part[r][ds][3][f4] = a3;
    *(float4*)&part[r][ds][4][f4] = a4;
    __syncthreads();

    if (wg < 80) {
        int gate = wg >> 4, fgi = wg & 15;
        float4 s = make_float4(0,0,0,0);
        #pragma unroll
        for (int d2 = 0; d2 < 8; d2++) {
            float4 v = *(const float4*)&part[r][d2][gate][fgi * 4];
            s.x += v.x; s.y += v.y; s.z += v.z; s.w += v.w;
        }
        *(float4*)&red[r][gate][fgi * 4] = s;
    }
    __syncthreads();

    float xh_v = 0.f, z_v = 0.f, dff = 0.f;
    if (wg < FF) {
        int f = wg;
        float xr = red[r][0][f] + __ldg(bxr + f);
        float xz = red[r][1][f] + __ldg(bxr + FF + f);
        xh_v     = red[r][2][f] + __ldg(bxr + 2*FF + f);
        float rg = sigm(xr + red[r][3][f] + __ldg(bnr + f));
        z_v      = sigm(xz + red[r][4][f] + __ldg(bnr + FF + f));
        dff = df_s[r][f];
        rdf_s[r][f] = rg * dff;
    }
    __syncthreads();

    float4 c = make_float4(0,0,0,0);
    #pragma unroll
    for (int dd = 0; dd < 8; dd++) {
        int d = ds * 8 + dd;
        float rd = rdf_s[r][d];
        float4 n2 = __ldg((const float4*)(Wnr + (2*FF + d)*FF + f4));
        c.x += rd*n2.x; c.y += rd*n2.y; c.z += rd*n2.z; c.w += rd*n2.w;
    }
    *(float4*)&part[r][ds][0][f4] = c;
    __syncthreads();

    if (wg < 16) {
        float4 s = make_float4(0,0,0,0);
        #pragma unroll
        for (int d2 = 0; d2 < 8; d2++) {
            float4 v = *(const float4*)&part[r][d2][0][wg * 4];
            s.x += v.x; s.y += v.y; s.z += v.z; s.w += v.w;
        }
        *(float4*)&red[r][5][wg * 4] = s;
    }
    __syncthreads();

    if (wg < FF) {
        float hc = tanhf(xh_v + red[r][5][wg] + __ldg(bnr + 2*FF + wg));
        gru_s[r][wg] = z_v * dff + (1.f - z_v) * hc;
    }
    __syncthreads();

    if (tid < FF)
        out[(long long)n * FF + tid] =
            tanhf(0.5f * (gru_s[0][tid] + gru_s[1][tid]));
}

extern "C" void kernel_launch(void* const* d_in, const int* in_sizes, int n_in,
                              void* d_out, int out_size) {
    (void)in_sizes; (void)n_in; (void)out_size;
    static_assert(ATTN_SMEM_BYTES < 227 * 1024, "smem too big");
    cudaFuncSetAttribute(attn_kernel,
                         cudaFuncAttributeMaxDynamicSharedMemorySize,
                         ATTN_SMEM_BYTES);
    attn_kernel<<<NN * RR, 256, ATTN_SMEM_BYTES>>>(
        d_in[0], d_in[1],
        (const float*)d_in[2],         // embed
        (const float*)d_in[3],         // w
        (const float*)d_in[4],         // qw
        (const float*)d_in[5]);        // kw
    gru_kernel<<<NN, 256>>>(
        d_in[0],
        (const float*)d_in[2],         // embed
        (const float*)d_in[6],         // Wx
        (const float*)d_in[7],         // Wn
        (const float*)d_in[8],         // bx
        (const float*)d_in[9],         // bn
        (float*)d_out);
}